// round 11
// baseline (speedup 1.0000x reference)
#include <cuda_runtime.h>
#include <cuda_bf16.h>
#include <math.h>
#include <stdint.h>

#define BB    2
#define SS    4096
#define HIDN  2048
#define HVN   32
#define HKN   16
#define CONVD 8192
#define KEYD  2048
#define VALD  4096
#define NCHK  64
#define MROWS (BB*SS)

// ---------------- device scratch ----------------
__device__ float g_mixed[(size_t)BB*SS*CONVD];
__device__ float g_z    [(size_t)BB*SS*VALD];
__device__ float g_qn   [(size_t)BB*HKN*SS*128];
__device__ float g_kn   [(size_t)BB*HKN*SS*128];
__device__ float g_v    [(size_t)BB*HVN*SS*128];
__device__ float g_core [(size_t)BB*HVN*SS*128];
__device__ float g_beta [(size_t)BB*SS*HVN];
__device__ float g_gg   [(size_t)BB*SS*HVN];

__device__ __nv_bfloat16 g_hs_hi [(size_t)MROWS*HIDN];
__device__ __nv_bfloat16 g_hs_lo [(size_t)MROWS*HIDN];
__device__ __nv_bfloat16 g_wqkv_hi[(size_t)CONVD*HIDN];  // [N,K]
__device__ __nv_bfloat16 g_wqkv_lo[(size_t)CONVD*HIDN];
__device__ __nv_bfloat16 g_wz_hi  [(size_t)VALD*HIDN];
__device__ __nv_bfloat16 g_wz_lo  [(size_t)VALD*HIDN];
__device__ __nv_bfloat16 g_wout_hi[(size_t)HIDN*VALD];
__device__ __nv_bfloat16 g_wout_lo[(size_t)HIDN*VALD];
__device__ __nv_bfloat16 g_act_hi [(size_t)MROWS*VALD];
__device__ __nv_bfloat16 g_act_lo [(size_t)MROWS*VALD];

// ---------------- helpers ----------------
__device__ __forceinline__ uint32_t smem_u32(const void* p) {
    uint32_t a;
    asm("{ .reg .u64 t; cvta.to.shared.u64 t, %1; cvt.u32.u64 %0, t; }" : "=r"(a) : "l"(p));
    return a;
}
__device__ __forceinline__ void ldsm4(uint32_t* r, uint32_t addr) {
    asm volatile("ldmatrix.sync.aligned.m8n8.x4.shared.b16 {%0,%1,%2,%3}, [%4];"
        : "=r"(r[0]), "=r"(r[1]), "=r"(r[2]), "=r"(r[3]) : "r"(addr));
}
__device__ __forceinline__ void mma16816(float* c, const uint32_t* a, const uint32_t* b) {
    asm volatile("mma.sync.aligned.m16n8k16.row.col.f32.bf16.bf16.f32 "
        "{%0,%1,%2,%3}, {%4,%5,%6,%7}, {%8,%9}, {%0,%1,%2,%3};"
        : "+f"(c[0]), "+f"(c[1]), "+f"(c[2]), "+f"(c[3])
        : "r"(a[0]), "r"(a[1]), "r"(a[2]), "r"(a[3]), "r"(b[0]), "r"(b[1]));
}
__device__ __forceinline__ void cp16(uint32_t dst, const void* src) {
    asm volatile("cp.async.cg.shared.global [%0], [%1], 16;" :: "r"(dst), "l"(src));
}

// ---------------- split kernels ----------------
__global__ __launch_bounds__(256) void split_kernel(
    const float* __restrict__ in, __nv_bfloat16* __restrict__ hi, __nv_bfloat16* __restrict__ lo, size_t n)
{
    size_t i = (size_t)blockIdx.x * 256 + threadIdx.x;
    size_t stride = (size_t)gridDim.x * 256;
    for (; i < n; i += stride) {
        float v = in[i];
        __nv_bfloat16 h = __float2bfloat16_rn(v);
        hi[i] = h;
        lo[i] = __float2bfloat16_rn(v - __bfloat162float(h));
    }
}

__global__ __launch_bounds__(256) void tsplit_all_kernel(
    const float* __restrict__ Wq, __nv_bfloat16* __restrict__ qh, __nv_bfloat16* __restrict__ ql,
    const float* __restrict__ Wz, __nv_bfloat16* __restrict__ zh, __nv_bfloat16* __restrict__ zl,
    const float* __restrict__ Wo, __nv_bfloat16* __restrict__ oh, __nv_bfloat16* __restrict__ ol)
{
    __shared__ float tile[32][33];
    int n = blockIdx.x;
    const float* W; __nv_bfloat16 *Thi, *Tlo; int K, N, bx, by;
    if (n < 16384)      { W = Wq; Thi = qh; Tlo = ql; K = HIDN; N = CONVD; bx = n & 255; by = n >> 8; }
    else if (n < 24576) { n -= 16384; W = Wz; Thi = zh; Tlo = zl; K = HIDN; N = VALD; bx = n & 127; by = n >> 7; }
    else                { n -= 24576; W = Wo; Thi = oh; Tlo = ol; K = VALD; N = HIDN; bx = n & 63;  by = n >> 6; }
    int tx = threadIdx.x & 31, ty = threadIdx.x >> 5;
    for (int i = ty; i < 32; i += 8)
        tile[i][tx] = W[(size_t)(by*32 + i) * N + bx*32 + tx];
    __syncthreads();
    for (int i = ty; i < 32; i += 8) {
        float v = tile[tx][i];
        __nv_bfloat16 h = __float2bfloat16_rn(v);
        size_t oi = (size_t)(bx*32 + i) * K + by*32 + tx;
        Thi[oi] = h;
        Tlo[oi] = __float2bfloat16_rn(v - __bfloat162float(h));
    }
}

// ---------------- HMMA bf16x3 GEMM: C[M,N] = A @ B^T ----------------
// 512 threads, tile 128(M)x256(N), BK=32, 3-stage cp.async pipeline, 1 sync/iter.
// stage layout (pitch 80B/row): Ahi[128] | Alo[128] | Bhi[256] | Blo[256] = 61440 B
#define G_PITCH   80
#define G_AHI     0
#define G_ALO     10240
#define G_BHI     20480
#define G_BLO     40960
#define G_STAGE   61440
#define GEMM_SMEM (3*G_STAGE)

__global__ __launch_bounds__(512, 1) void hmma_gemm_kernel(
    const __nv_bfloat16* __restrict__ Ahi, const __nv_bfloat16* __restrict__ Alo,
    const __nv_bfloat16* __restrict__ Bhi, const __nv_bfloat16* __restrict__ Blo,
    float* __restrict__ C, int M, int N, int K)
{
    extern __shared__ char smem[];
    uint32_t sb = smem_u32(smem);
    int t = threadIdx.x;
    int m0 = blockIdx.x * 128;
    int n0 = blockIdx.y * 256;
    int w = t >> 5, l = t & 31;
    int wm = w & 3, wn = w >> 2;    // 4 warps M x 4 warps N; warp tile 32(M) x 64(N)

    float acc[2][8][4];
#pragma unroll
    for (int i = 0; i < 2; i++)
#pragma unroll
        for (int j = 0; j < 8; j++)
#pragma unroll
            for (int r = 0; r < 4; r++) acc[i][j][r] = 0.f;

    int KT = K >> 5;

    auto load_stage = [&](int s, int k0) {
        uint32_t stb = sb + s * G_STAGE;
#pragma unroll
        for (int c = 0; c < 6; c++) {
            int idx = t + c * 512;          // 0..3071
            int ch = idx & 3;
            int rr = idx >> 2;              // 0..767
            const __nv_bfloat16* src; uint32_t dstb; int row, rowg;
            if (rr < 128)      { src = Ahi; dstb = stb + G_AHI; row = rr;       rowg = m0 + row; }
            else if (rr < 256) { src = Alo; dstb = stb + G_ALO; row = rr - 128; rowg = m0 + row; }
            else if (rr < 512) { src = Bhi; dstb = stb + G_BHI; row = rr - 256; rowg = n0 + row; }
            else               { src = Blo; dstb = stb + G_BLO; row = rr - 512; rowg = n0 + row; }
            cp16(dstb + row * G_PITCH + ch * 16, src + (size_t)rowg * K + k0 + ch * 8);
        }
        asm volatile("cp.async.commit_group;");
    };

    // prologue: stages 0,1
    load_stage(0, 0);
    if (KT > 1) load_stage(1, 32);
    else        asm volatile("cp.async.commit_group;");

    int a_off = (wm * 32 + (l & 15)) * G_PITCH + ((l >> 4) * 16);
    int b_off = (wn * 64 + (l & 7) + ((l >> 4) << 3)) * G_PITCH + (((l >> 3) & 1) * 16);

    for (int kt = 0; kt < KT; kt++) {
        asm volatile("cp.async.wait_group 1;");
        __syncthreads();
        // issue stage kt+2 into slot (kt+2)%3 == (kt-1)%3 (drained: all warps passed sync above)
        if (kt + 2 < KT) load_stage((kt + 2) % 3, (kt + 2) << 5);
        else             asm volatile("cp.async.commit_group;");

        uint32_t stb = sb + (kt % 3) * G_STAGE;
#pragma unroll
        for (int ks = 0; ks < 2; ks++) {
            uint32_t ah[2][4], al[2][4];
#pragma unroll
            for (int mt = 0; mt < 2; mt++) {
                uint32_t aa = stb + G_AHI + a_off + mt * 16 * G_PITCH + ks * 32;
                ldsm4(ah[mt], aa);
                ldsm4(al[mt], aa + G_ALO);
            }
#pragma unroll
            for (int ntp = 0; ntp < 4; ntp++) {
                uint32_t ba = stb + G_BHI + b_off + ntp * 16 * G_PITCH + ks * 32;
                uint32_t bh[4], bl[4];
                ldsm4(bh, ba);
                ldsm4(bl, ba + (G_BLO - G_BHI));
#pragma unroll
                for (int mt = 0; mt < 2; mt++) {
                    mma16816(acc[mt][2*ntp],   ah[mt], bh);
                    mma16816(acc[mt][2*ntp],   ah[mt], bl);
                    mma16816(acc[mt][2*ntp],   al[mt], bh);
                    mma16816(acc[mt][2*ntp+1], ah[mt], bh + 2);
                    mma16816(acc[mt][2*ntp+1], ah[mt], bl + 2);
                    mma16816(acc[mt][2*ntp+1], al[mt], bh + 2);
                }
            }
        }
        // no trailing sync: next iter's sync guards slot recycling
    }

#pragma unroll
    for (int mt = 0; mt < 2; mt++) {
        int row = m0 + wm * 32 + mt * 16 + (l >> 2);
        int colb = n0 + wn * 64 + 2 * (l & 3);
#pragma unroll
        for (int nt = 0; nt < 8; nt++) {
            int col = colb + nt * 8;
            float2 v0; v0.x = acc[mt][nt][0]; v0.y = acc[mt][nt][1];
            float2 v1; v1.x = acc[mt][nt][2]; v1.y = acc[mt][nt][3];
            *(float2*)&C[(size_t)row * N + col] = v0;
            *(float2*)&C[(size_t)(row + 8) * N + col] = v1;
        }
    }
}

// ---------------- beta / g projections ----------------
#define BG_RG 4
__global__ __launch_bounds__(256) void bg_kernel(
    const float* __restrict__ hs, const float* __restrict__ W_b, const float* __restrict__ W_a,
    const float* __restrict__ dt_bias, const float* __restrict__ A_log,
    float* __restrict__ beta, float* __restrict__ gg)
{
    __shared__ float hsm[BG_RG * HIDN];
    __shared__ float red[4 * BG_RG * 64];
    int r0 = blockIdx.x * BG_RG;
    int t = threadIdx.x;
    for (int o = t; o < BG_RG * HIDN / 4; o += 256)
        ((float4*)hsm)[o] = ((const float4*)(hs + (size_t)r0 * HIDN))[o];
    __syncthreads();

    int out = t & 63, part = t >> 6;
    const float* Wp = (out < 32) ? (W_b + out) : (W_a + out - 32);
    float acc[BG_RG];
#pragma unroll
    for (int r = 0; r < BG_RG; r++) acc[r] = 0.f;
    int kbase = part * (HIDN / 4);
    for (int kk = 0; kk < HIDN / 4; kk++) {
        int k = kbase + kk;
        float w2 = Wp[(size_t)k * 32];
#pragma unroll
        for (int r = 0; r < BG_RG; r++) acc[r] += hsm[r * HIDN + k] * w2;
    }
#pragma unroll
    for (int r = 0; r < BG_RG; r++) red[(part * BG_RG + r) * 64 + out] = acc[r];
    __syncthreads();

    int rr = t >> 6, oo = t & 63;
    float s = red[(0*BG_RG+rr)*64+oo] + red[(1*BG_RG+rr)*64+oo]
            + red[(2*BG_RG+rr)*64+oo] + red[(3*BG_RG+rr)*64+oo];
    size_t row = (size_t)r0 + rr;
    if (oo < 32) {
        beta[row * 32 + oo] = 1.f / (1.f + expf(-s));
    } else {
        int h = oo - 32;
        float x = s + dt_bias[h];
        float sp = (x > 20.f) ? x : log1pf(expf(x));
        gg[row * 32 + h] = -expf(A_log[h]) * sp;
    }
}

// ---------------- conv1d(K=4 causal) + SiLU + split + l2norm(q,k) ----------------
__global__ __launch_bounds__(128) void conv_silu_kernel(
    const float* __restrict__ mixed, const float* __restrict__ conv_w,
    float* __restrict__ qn, float* __restrict__ kn, float* __restrict__ vout)
{
    int unit = blockIdx.x;
    int s0 = blockIdx.y * 8;
    int b = blockIdx.z;
    int d = threadIdx.x;
    int base = (unit < 16) ? unit * 128
             : (unit < 32) ? KEYD + (unit - 16) * 128
             : 2 * KEYD + (unit - 32) * 128;
    int c = base + d;
    const float* mb = mixed + (size_t)b * SS * CONVD + c;

    float m[11];
#pragma unroll
    for (int j = 0; j < 11; j++) {
        int sp = s0 + j - 3;
        m[j] = (sp >= 0) ? mb[(size_t)sp * CONVD] : 0.f;
    }
    float w0 = conv_w[(size_t)c*4+0], w1 = conv_w[(size_t)c*4+1],
          w2 = conv_w[(size_t)c*4+2], w3 = conv_w[(size_t)c*4+3];
    float xs[8];
#pragma unroll
    for (int sp = 0; sp < 8; sp++) {
        float a = w0*m[sp] + w1*m[sp+1] + w2*m[sp+2] + w3*m[sp+3];
        xs[sp] = a / (1.f + expf(-a));
    }

    if (unit < 32) {
        __shared__ float red[8][4];
#pragma unroll
        for (int sp = 0; sp < 8; sp++) {
            float ss = xs[sp]*xs[sp];
#pragma unroll
            for (int off = 16; off > 0; off >>= 1) ss += __shfl_down_sync(0xffffffffu, ss, off);
            if ((d & 31) == 0) red[sp][d >> 5] = ss;
        }
        __syncthreads();
        float* dst; float extra;
        if (unit < 16) { dst = qn + (((size_t)(b*HKN+unit))*SS)*128; extra = 0.08838834764831845f; }
        else           { dst = kn + (((size_t)(b*HKN+unit-16))*SS)*128; extra = 1.f; }
#pragma unroll
        for (int sp = 0; sp < 8; sp++) {
            float tot = red[sp][0]+red[sp][1]+red[sp][2]+red[sp][3];
            float scale = rsqrtf(tot + 1e-6f) * extra;
            dst[(size_t)(s0+sp)*128 + d] = xs[sp] * scale;
        }
    } else {
        float* dst = vout + (((size_t)(b*HVN+unit-32))*SS)*128;
#pragma unroll
        for (int sp = 0; sp < 8; sp++)
            dst[(size_t)(s0+sp)*128 + d] = xs[sp];
    }
}

// ---------------- chunked gated delta rule, DV split x2, W/A on tensor cores ----------------
#define DBF_OFF   148992
#define DBF_ARR   17408
#define DBF_PITCH 272
#define DELTA_SMEM_BYTES (148992 + 4*DBF_ARR)

__global__ __launch_bounds__(256, 1) void delta_kernel(
    const float* __restrict__ qn, const float* __restrict__ kn,
    const float* __restrict__ vv, const float* __restrict__ beta,
    const float* __restrict__ gg, float* __restrict__ core)
{
    extern __shared__ float sm[];
    char* smc = (char*)sm;
    uint32_t sbase = smem_u32(sm);
    float* st  = sm;          // [128][64]
    float* KT  = st + 8192;   // [128][65]
    float* Qs  = KT + 8320;   // [64][128]
    float* Vs  = Qs + 8192;   // [64][64]
    float* Wm  = Vs + 4096;   // [64][64]
    float* Am  = Wm + 4096;   // [64][64]
    float* gcs = Am + 4096;
    float* bet = gcs + 64;
    float* egs = bet + 64;
    float* edl = egs + 64;

    int t = threadIdx.x;
    int wrp = t >> 5, l = t & 31;
    int vs = blockIdx.x & 1;
    int h  = (blockIdx.x >> 1) & 31;
    int b  = blockIdx.x >> 6;
    int vo = vs * 64;
    int hk = h >> 1;
    const float* qb = qn + (size_t)(b*HKN+hk)*SS*128;
    const float* kb = kn + (size_t)(b*HKN+hk)*SS*128;
    const float* vb = vv + (size_t)(b*HVN+h)*SS*128;
    const float* bp = beta + (size_t)b*SS*HVN + h;
    const float* gp = gg   + (size_t)b*SS*HVN + h;
    float* cb = core + (size_t)(b*HVN+h)*SS*128;

    for (int i = t; i < 8192; i += 256) st[i] = 0.f;
    __syncthreads();

    for (int ck = 0; ck < NCHK; ck++) {
        size_t srow = (size_t)ck * 64;
        const float* qr = qb + srow*128;
        const float* kr = kb + srow*128;
        const float* vr = vb + srow*128;
        for (int idx = t; idx < 8192; idx += 256) {
            int i = idx >> 7, d = idx & 127;
            float kvv = kr[idx];
            float qvv = qr[idx];
            KT[d*65 + i] = kvv;
            Qs[idx] = qvv;
            __nv_bfloat16 kh = __float2bfloat16_rn(kvv);
            __nv_bfloat16 qh = __float2bfloat16_rn(qvv);
            int ro = i*DBF_PITCH + d*2;
            *(__nv_bfloat16*)(smc + DBF_OFF + 0*DBF_ARR + ro) = kh;
            *(__nv_bfloat16*)(smc + DBF_OFF + 1*DBF_ARR + ro) = __float2bfloat16_rn(kvv - __bfloat162float(kh));
            *(__nv_bfloat16*)(smc + DBF_OFF + 2*DBF_ARR + ro) = qh;
            *(__nv_bfloat16*)(smc + DBF_OFF + 3*DBF_ARR + ro) = __float2bfloat16_rn(qvv - __bfloat162float(qh));
        }
        for (int idx = t; idx < 4096; idx += 256) {
            int i = idx >> 6, c = idx & 63;
            Vs[idx] = vr[i*128 + vo + c];
        }
        if (t < 64) {
            bet[t] = bp[(srow + t)*HVN];
            edl[t] = gp[(srow + t)*HVN];
        }
        __syncthreads();
        if (t == 0) {
            float r = 0.f;
            for (int i = 0; i < 64; i++) { r += edl[i]; gcs[i] = r; }
        }
        __syncthreads();
        if (t < 64) {
            egs[t] = expf(gcs[t]);
            edl[t] = expf(gcs[63] - gcs[t]);
        }
        __syncthreads();

        // ---- W/A via HMMA bf16x3 ----
        {
            float acc[2][4][4];
#pragma unroll
            for (int a1 = 0; a1 < 2; a1++)
#pragma unroll
                for (int a2 = 0; a2 < 4; a2++)
#pragma unroll
                    for (int a3 = 0; a3 < 4; a3++) acc[a1][a2][a3] = 0.f;

            uint32_t a_row = (l & 15);
            uint32_t a_col = (l >> 4) * 16;
            uint32_t b_row = (l & 7) + ((l >> 4) << 3);
            uint32_t b_col = ((l >> 3) & 1) * 16;
#pragma unroll
            for (int tt = 0; tt < 2; tt++) {
                int tile = wrp + tt*8;
                int Dsel = tile >> 3;
                int sub = tile & 7;
                int r0 = (sub >> 1) << 4, c0g = (sub & 1) << 5;
                uint32_t ahb = sbase + DBF_OFF + (Dsel ? 2*DBF_ARR : 0);
#pragma unroll
                for (int kt = 0; kt < 8; kt++) {
                    uint32_t aaddr = ahb + (r0 + a_row)*DBF_PITCH + kt*32 + a_col;
                    uint32_t ah[4], al[4];
                    ldsm4(ah, aaddr);
                    ldsm4(al, aaddr + DBF_ARR);
#pragma unroll
                    for (int nn = 0; nn < 2; nn++) {
                        uint32_t baddr = sbase + DBF_OFF + (c0g + nn*16 + b_row)*DBF_PITCH + kt*32 + b_col;
                        uint32_t bh[4], bl[4];
                        ldsm4(bh, baddr);
                        ldsm4(bl, baddr + DBF_ARR);
                        mma16816(acc[tt][2*nn],   ah, bh);
                        mma16816(acc[tt][2*nn],   ah, bl);
                        mma16816(acc[tt][2*nn],   al, bh);
                        mma16816(acc[tt][2*nn+1], ah, bh + 2);
                        mma16816(acc[tt][2*nn+1], ah, bl + 2);
                        mma16816(acc[tt][2*nn+1], al, bh + 2);
                    }
                }
#pragma unroll
                for (int n8 = 0; n8 < 4; n8++) {
#pragma unroll
                    for (int e = 0; e < 4; e++) {
                        int row = r0 + (l >> 2) + ((e >> 1) ? 8 : 0);
                        int col = c0g + n8*8 + 2*(l & 3) + (e & 1);
                        float dot = acc[tt][n8][e];
                        if (Dsel == 0) {
                            float outv = 0.f;
                            if (col < row) outv = bet[row] * expf(gcs[row] - gcs[col]) * dot;
                            Wm[row*64 + col] = outv;
                        } else {
                            float outv = 0.f;
                            if (col <= row) outv = expf(gcs[row] - gcs[col]) * dot;
                            Am[row*64 + col] = outv;
                        }
                    }
                }
            }
        }
        // ---- X = beta*(v - e^{gc} * (k @ st)) ----
        {
            int r0 = (t >> 3) * 2, c0 = (t & 7) * 8;
            float acc[2][8];
#pragma unroll
            for (int i = 0; i < 2; i++)
#pragma unroll
                for (int j = 0; j < 8; j++) acc[i][j] = 0.f;
            for (int d = 0; d < 128; d++) {
                float kv0 = KT[d*65 + r0], kv1 = KT[d*65 + r0 + 1];
                float4 s0 = *(float4*)&st[d*64 + c0];
                float4 s1 = *(float4*)&st[d*64 + c0 + 4];
                float sv[8] = {s0.x,s0.y,s0.z,s0.w,s1.x,s1.y,s1.z,s1.w};
#pragma unroll
                for (int j = 0; j < 8; j++) {
                    acc[0][j] += kv0*sv[j];
                    acc[1][j] += kv1*sv[j];
                }
            }
            __syncthreads();
#pragma unroll
            for (int i = 0; i < 2; i++) {
                int r = r0 + i; float bi = bet[r], e = egs[r];
#pragma unroll
                for (int j = 0; j < 8; j++) {
                    int c = c0 + j;
                    Vs[r*64 + c] = bi*(Vs[r*64 + c] - e*acc[i][j]);
                }
            }
        }
        __syncthreads();
        // ---- forward substitution ----
        if (t < 64) {
            float x[64];
#pragma unroll
            for (int i = 0; i < 64; i++) {
                float a0 = Vs[i*64 + t], a1 = 0.f;
                int j = 0;
#pragma unroll
                for (; j + 2 <= i; j += 2) {
                    a0 -= Wm[i*64 + j]   * x[j];
                    a1 -= Wm[i*64 + j+1] * x[j+1];
                }
                if (j < i) a0 -= Wm[i*64 + j] * x[j];
                x[i] = a0 + a1;
            }
#pragma unroll
            for (int i = 0; i < 64; i++) Vs[i*64 + t] = x[i];
        }
        __syncthreads();
        // ---- out = e^{gc}*(q@st) + Am@v_new ----
        {
            int r0 = (t >> 3) * 2, c0 = (t & 7) * 8;
            float o1[2][8], o2[2][8];
#pragma unroll
            for (int i = 0; i < 2; i++)
#pragma unroll
                for (int j = 0; j < 8; j++) { o1[i][j] = 0.f; o2[i][j] = 0.f; }
            for (int d = 0; d < 128; d++) {
                float q0 = Qs[r0*128 + d], q1 = Qs[(r0+1)*128 + d];
                float4 s0 = *(float4*)&st[d*64 + c0];
                float4 s1 = *(float4*)&st[d*64 + c0 + 4];
                float sv[8] = {s0.x,s0.y,s0.z,s0.w,s1.x,s1.y,s1.z,s1.w};
#pragma unroll
                for (int j = 0; j < 8; j++) {
                    o1[0][j] += q0*sv[j];
                    o1[1][j] += q1*sv[j];
                }
            }
            for (int jj = 0; jj < 64; jj++) {
                float a0 = Am[r0*64 + jj], a1 = Am[(r0+1)*64 + jj];
                float4 v0 = *(float4*)&Vs[jj*64 + c0];
                float4 v1 = *(float4*)&Vs[jj*64 + c0 + 4];
                float vw[8] = {v0.x,v0.y,v0.z,v0.w,v1.x,v1.y,v1.z,v1.w};
#pragma unroll
                for (int j = 0; j < 8; j++) {
                    o2[0][j] += a0*vw[j];
                    o2[1][j] += a1*vw[j];
                }
            }
#pragma unroll
            for (int i = 0; i < 2; i++) {
                int r = r0 + i; float e = egs[r];
#pragma unroll
                for (int j = 0; j < 8; j += 4) {
                    float4 v;
                    v.x = e*o1[i][j]   + o2[i][j];
                    v.y = e*o1[i][j+1] + o2[i][j+1];
                    v.z = e*o1[i][j+2] + o2[i][j+2];
                    v.w = e*o1[i][j+3] + o2[i][j+3];
                    *(float4*)&cb[(srow + r)*128 + vo + c0 + j] = v;
                }
            }
        }
        __syncthreads();
        // ---- state update ----
        {
            int d0 = (t >> 3) * 4, v0 = (t & 7) * 8;
            float acc[4][8];
#pragma unroll
            for (int i = 0; i < 4; i++)
#pragma unroll
                for (int j = 0; j < 8; j++) acc[i][j] = 0.f;
            for (int i = 0; i < 64; i++) {
                float el = edl[i];
                float kv[4];
#pragma unroll
                for (int x2 = 0; x2 < 4; x2++) kv[x2] = KT[(d0+x2)*65 + i] * el;
                float4 a = *(float4*)&Vs[i*64 + v0];
                float4 bq = *(float4*)&Vs[i*64 + v0 + 4];
                float vw[8] = {a.x,a.y,a.z,a.w,bq.x,bq.y,bq.z,bq.w};
#pragma unroll
                for (int x2 = 0; x2 < 4; x2++)
#pragma unroll
                    for (int y = 0; y < 8; y++) acc[x2][y] += kv[x2]*vw[y];
            }
            float egl = expf(gcs[63]);
#pragma unroll
            for (int x2 = 0; x2 < 4; x2++)
#pragma unroll
                for (int y = 0; y < 8; y += 4) {
                    float4 s = *(float4*)&st[(d0+x2)*64 + v0 + y];
                    s.x = s.x*egl + acc[x2][y];
                    s.y = s.y*egl + acc[x2][y+1];
                    s.z = s.z*egl + acc[x2][y+2];
                    s.w = s.w*egl + acc[x2][y+3];
                    *(float4*)&st[(d0+x2)*64 + v0 + y] = s;
                }
        }
        __syncthreads();
    }
}

// ---------------- gated RMSNorm + SiLU(z) gate -> bf16 hi/lo ----------------
__global__ __launch_bounds__(128) void normgate_kernel(
    const float* __restrict__ core, const float* __restrict__ z,
    const float* __restrict__ norm_weight,
    __nv_bfloat16* __restrict__ act_hi, __nv_bfloat16* __restrict__ act_lo)
{
    int s = blockIdx.x, h = blockIdx.y, b = blockIdx.z;
    int d = threadIdx.x;
    __shared__ float red[4];
    size_t ci = ((size_t)(b*HVN + h)*SS + s)*128 + d;
    float v = core[ci];
    float ss = v*v;
#pragma unroll
    for (int off = 16; off > 0; off >>= 1) ss += __shfl_down_sync(0xffffffffu, ss, off);
    if ((d & 31) == 0) red[d >> 5] = ss;
    __syncthreads();
    float var = (red[0]+red[1]+red[2]+red[3]) * (1.f/128.f);
    float scale = rsqrtf(var + 1e-6f) * norm_weight[d];
    size_t zi = ((size_t)b*SS + s)*VALD + h*128 + d;
    float zv = z[zi];
    float gate = zv / (1.f + expf(-zv));
    float val = v * scale * gate;
    __nv_bfloat16 hv = __float2bfloat16_rn(val);
    act_hi[zi] = hv;
    act_lo[zi] = __float2bfloat16_rn(val - __bfloat162float(hv));
}

extern "C" void kernel_launch(void* const* d_in, const int* in_sizes, int n_in,
                              void* d_out, int out_size) {
    const float* hs     = (const float*)d_in[0];
    const float* W_qkv  = (const float*)d_in[1];
    const float* conv_w = (const float*)d_in[2];
    const float* W_z    = (const float*)d_in[3];
    const float* W_b    = (const float*)d_in[4];
    const float* W_a    = (const float*)d_in[5];
    const float* dt_b   = (const float*)d_in[6];
    const float* A_log  = (const float*)d_in[7];
    const float* normw  = (const float*)d_in[8];
    const float* W_out  = (const float*)d_in[9];
    float* out = (float*)d_out;

    float *mixed, *z, *qn, *kn, *v, *core, *beta, *gg;
    cudaGetSymbolAddress((void**)&mixed, g_mixed);
    cudaGetSymbolAddress((void**)&z,     g_z);
    cudaGetSymbolAddress((void**)&qn,    g_qn);
    cudaGetSymbolAddress((void**)&kn,    g_kn);
    cudaGetSymbolAddress((void**)&v,     g_v);
    cudaGetSymbolAddress((void**)&core,  g_core);
    cudaGetSymbolAddress((void**)&beta,  g_beta);
    cudaGetSymbolAddress((void**)&gg,    g_gg);

    __nv_bfloat16 *hs_hi, *hs_lo, *wqkv_hi, *wqkv_lo, *wz_hi, *wz_lo, *wout_hi, *wout_lo, *act_hi, *act_lo;
    cudaGetSymbolAddress((void**)&hs_hi,   g_hs_hi);
    cudaGetSymbolAddress((void**)&hs_lo,   g_hs_lo);
    cudaGetSymbolAddress((void**)&wqkv_hi, g_wqkv_hi);
    cudaGetSymbolAddress((void**)&wqkv_lo, g_wqkv_lo);
    cudaGetSymbolAddress((void**)&wz_hi,   g_wz_hi);
    cudaGetSymbolAddress((void**)&wz_lo,   g_wz_lo);
    cudaGetSymbolAddress((void**)&wout_hi, g_wout_hi);
    cudaGetSymbolAddress((void**)&wout_lo, g_wout_lo);
    cudaGetSymbolAddress((void**)&act_hi,  g_act_hi);
    cudaGetSymbolAddress((void**)&act_lo,  g_act_lo);

    cudaFuncSetAttribute(delta_kernel, cudaFuncAttributeMaxDynamicSharedMemorySize, DELTA_SMEM_BYTES);
    cudaFuncSetAttribute(hmma_gemm_kernel, cudaFuncAttributeMaxDynamicSharedMemorySize, GEMM_SMEM);

    static cudaStream_t s2 = nullptr;
    static cudaEvent_t e_fork = nullptr, e_g2 = nullptr;
    if (s2 == nullptr) {
        cudaStreamCreateWithFlags(&s2, cudaStreamNonBlocking);
        cudaEventCreateWithFlags(&e_fork, cudaEventDisableTiming);
        cudaEventCreateWithFlags(&e_g2, cudaEventDisableTiming);
    }

    // 0) weight transposes+splits (one launch), hs split
    tsplit_all_kernel<<<32768, 256>>>(W_qkv, wqkv_hi, wqkv_lo, W_z, wz_hi, wz_lo, W_out, wout_hi, wout_lo);
    split_kernel<<<2048, 256>>>(hs, hs_hi, hs_lo, (size_t)MROWS*HIDN);

    // 1) mixed = hs @ W_qkv
    hmma_gemm_kernel<<<dim3(MROWS/128, CONVD/256), 512, GEMM_SMEM>>>(
        hs_hi, hs_lo, wqkv_hi, wqkv_lo, mixed, MROWS, CONVD, HIDN);

    // fork: z-projection on side stream
    cudaEventRecord(e_fork, 0);
    cudaStreamWaitEvent(s2, e_fork, 0);
    hmma_gemm_kernel<<<dim3(MROWS/128, VALD/256), 512, GEMM_SMEM, s2>>>(
        hs_hi, hs_lo, wz_hi, wz_lo, z, MROWS, VALD, HIDN);
    cudaEventRecord(e_g2, s2);

    // main chain
    bg_kernel<<<MROWS/BG_RG, 256>>>(hs, W_b, W_a, dt_b, A_log, beta, gg);
    conv_silu_kernel<<<dim3(64, SS/8, BB), 128>>>(mixed, conv_w, qn, kn, v);
    delta_kernel<<<BB*HVN*2, 256, DELTA_SMEM_BYTES>>>(qn, kn, v, beta, gg, core);

    // join: normgate needs z
    cudaStreamWaitEvent(0, e_g2, 0);
    normgate_kernel<<<dim3(SS, HVN, BB), 128>>>(core, z, normw, act_hi, act_lo);

    // out = act @ W_out
    hmma_gemm_kernel<<<dim3(MROWS/128, HIDN/256), 512, GEMM_SMEM>>>(
        act_hi, act_lo, wout_hi, wout_lo, out, MROWS, HIDN, VALD);
}

// round 12
// speedup vs baseline: 1.3462x; 1.3462x over previous
#include <cuda_runtime.h>
#include <cuda_bf16.h>
#include <cuda_fp16.h>
#include <math.h>
#include <stdint.h>

#define BB    2
#define SS    4096
#define HIDN  2048
#define HVN   32
#define HKN   16
#define CONVD 8192
#define KEYD  2048
#define VALD  4096
#define NCHK  64
#define MROWS (BB*SS)

// ---------------- device scratch ----------------
__device__ float g_mixed[(size_t)BB*SS*CONVD];
__device__ float g_z    [(size_t)BB*SS*VALD];
__device__ float g_qn   [(size_t)BB*HKN*SS*128];
__device__ float g_kn   [(size_t)BB*HKN*SS*128];
__device__ float g_v    [(size_t)BB*HVN*SS*128];
__device__ float g_core [(size_t)BB*HVN*SS*128];
__device__ float g_beta [(size_t)BB*SS*HVN];
__device__ float g_gg   [(size_t)BB*SS*HVN];

__device__ __half g_hs_hi [(size_t)MROWS*HIDN];
__device__ __half g_hs_lo [(size_t)MROWS*HIDN];
__device__ __half g_wqkv_h[(size_t)CONVD*HIDN];  // [N,K]
__device__ __half g_wz_h  [(size_t)VALD*HIDN];
__device__ __half g_wout_h[(size_t)HIDN*VALD];
__device__ __half g_act_hi[(size_t)MROWS*VALD];
__device__ __half g_act_lo[(size_t)MROWS*VALD];

// ---------------- helpers ----------------
__device__ __forceinline__ uint32_t smem_u32(const void* p) {
    uint32_t a;
    asm("{ .reg .u64 t; cvta.to.shared.u64 t, %1; cvt.u32.u64 %0, t; }" : "=r"(a) : "l"(p));
    return a;
}
__device__ __forceinline__ void ldsm4(uint32_t* r, uint32_t addr) {
    asm volatile("ldmatrix.sync.aligned.m8n8.x4.shared.b16 {%0,%1,%2,%3}, [%4];"
        : "=r"(r[0]), "=r"(r[1]), "=r"(r[2]), "=r"(r[3]) : "r"(addr));
}
__device__ __forceinline__ void mma16816f(float* c, const uint32_t* a, const uint32_t* b) {
    asm volatile("mma.sync.aligned.m16n8k16.row.col.f32.f16.f16.f32 "
        "{%0,%1,%2,%3}, {%4,%5,%6,%7}, {%8,%9}, {%0,%1,%2,%3};"
        : "+f"(c[0]), "+f"(c[1]), "+f"(c[2]), "+f"(c[3])
        : "r"(a[0]), "r"(a[1]), "r"(a[2]), "r"(a[3]), "r"(b[0]), "r"(b[1]));
}
__device__ __forceinline__ void mma16816b(float* c, const uint32_t* a, const uint32_t* b) {
    asm volatile("mma.sync.aligned.m16n8k16.row.col.f32.bf16.bf16.f32 "
        "{%0,%1,%2,%3}, {%4,%5,%6,%7}, {%8,%9}, {%0,%1,%2,%3};"
        : "+f"(c[0]), "+f"(c[1]), "+f"(c[2]), "+f"(c[3])
        : "r"(a[0]), "r"(a[1]), "r"(a[2]), "r"(a[3]), "r"(b[0]), "r"(b[1]));
}
__device__ __forceinline__ void cp16(uint32_t dst, const void* src) {
    asm volatile("cp.async.cg.shared.global [%0], [%1], 16;" :: "r"(dst), "l"(src));
}

// ---------------- split kernels (fp16 hi/lo) ----------------
__global__ __launch_bounds__(256) void split_kernel(
    const float* __restrict__ in, __half* __restrict__ hi, __half* __restrict__ lo, size_t n)
{
    size_t i = (size_t)blockIdx.x * 256 + threadIdx.x;
    size_t stride = (size_t)gridDim.x * 256;
    for (; i < n; i += stride) {
        float v = in[i];
        __half h = __float2half_rn(v);
        hi[i] = h;
        lo[i] = __float2half_rn(v - __half2float(h));
    }
}

// all three weights: W[K,N] -> [N,K] single fp16
__global__ __launch_bounds__(256) void tsplit_all_kernel(
    const float* __restrict__ Wq, __half* __restrict__ qh,
    const float* __restrict__ Wz, __half* __restrict__ zh,
    const float* __restrict__ Wo, __half* __restrict__ oh)
{
    __shared__ float tile[32][33];
    int n = blockIdx.x;
    const float* W; __half* Thi; int K, N, bx, by;
    if (n < 16384)      { W = Wq; Thi = qh; K = HIDN; N = CONVD; bx = n & 255; by = n >> 8; }
    else if (n < 24576) { n -= 16384; W = Wz; Thi = zh; K = HIDN; N = VALD; bx = n & 127; by = n >> 7; }
    else                { n -= 24576; W = Wo; Thi = oh; K = VALD; N = HIDN; bx = n & 63;  by = n >> 6; }
    int tx = threadIdx.x & 31, ty = threadIdx.x >> 5;
    for (int i = ty; i < 32; i += 8)
        tile[i][tx] = W[(size_t)(by*32 + i) * N + bx*32 + tx];
    __syncthreads();
    for (int i = ty; i < 32; i += 8)
        Thi[(size_t)(bx*32 + i) * K + by*32 + tx] = __float2half_rn(tile[tx][i]);
}

// ---------------- HMMA fp16x2 GEMM: C[M,N] = A @ B^T ----------------
// A = Ahi+Alo fp16 [M,K]; B single fp16 [N,K]; C fp32.
// Tile 128x128x32, 256 thr, 2-stage, 2 CTAs/SM.
#define GS_ROW   80
#define GS_ARR   (128*GS_ROW)   // 10240
#define GS_STAGE (3*GS_ARR)     // 30720: Ahi | Alo | B
#define GEMM_SMEM (2*GS_STAGE)

__global__ __launch_bounds__(256, 2) void hmma_gemm_kernel(
    const __half* __restrict__ Ahi, const __half* __restrict__ Alo,
    const __half* __restrict__ Bh,
    float* __restrict__ C, int M, int N, int K)
{
    extern __shared__ char smem[];
    uint32_t sb = smem_u32(smem);
    int t = threadIdx.x;
    int m0 = blockIdx.x * 128;
    int n0 = blockIdx.y * 128;
    int w = t >> 5, l = t & 31;
    int wm = w & 3, wn = w >> 2;

    const __half* srcs[3] = { Ahi, Alo, Bh };
    int rowbase[3];
    rowbase[0] = m0; rowbase[1] = m0; rowbase[2] = n0;

    float acc[2][8][4];
#pragma unroll
    for (int i = 0; i < 2; i++)
#pragma unroll
        for (int j = 0; j < 8; j++)
#pragma unroll
            for (int r = 0; r < 4; r++) acc[i][j][r] = 0.f;

    int KT = K >> 5;

    auto load_stage = [&](int s, int k0) {
        uint32_t stb = sb + s * GS_STAGE;
#pragma unroll
        for (int c = 0; c < 6; c++) {
            int idx = t + c * 256;          // 0..1535
            int arr = idx >> 9;             // 0..2
            int within = idx & 511;
            int row = within >> 2, ch = within & 3;
            const __half* src = srcs[arr] + (size_t)(rowbase[arr] + row) * K + k0 + ch * 8;
            cp16(stb + arr * GS_ARR + row * GS_ROW + ch * 16, src);
        }
        asm volatile("cp.async.commit_group;");
    };

    load_stage(0, 0);

    int a_off = (wm * 32 + (l & 15)) * GS_ROW + ((l >> 4) * 16);
    int b_off = (wn * 64 + (l & 7) + ((l >> 4) << 3)) * GS_ROW + (((l >> 3) & 1) * 16);

    for (int kt = 0; kt < KT; kt++) {
        if (kt + 1 < KT) load_stage((kt + 1) & 1, (kt + 1) << 5);
        if (kt + 1 < KT) asm volatile("cp.async.wait_group 1;");
        else             asm volatile("cp.async.wait_group 0;");
        __syncthreads();

        uint32_t stb = sb + (kt & 1) * GS_STAGE;
#pragma unroll
        for (int ks = 0; ks < 2; ks++) {
            uint32_t ah[2][4], al[2][4];
#pragma unroll
            for (int mt = 0; mt < 2; mt++) {
                uint32_t aa = stb + a_off + mt * 16 * GS_ROW + ks * 32;
                ldsm4(ah[mt], aa);
                ldsm4(al[mt], aa + GS_ARR);
            }
#pragma unroll
            for (int ntp = 0; ntp < 4; ntp++) {
                uint32_t ba = stb + 2 * GS_ARR + b_off + ntp * 16 * GS_ROW + ks * 32;
                uint32_t bh[4];
                ldsm4(bh, ba);
#pragma unroll
                for (int mt = 0; mt < 2; mt++) {
                    mma16816f(acc[mt][2*ntp],   ah[mt], bh);
                    mma16816f(acc[mt][2*ntp],   al[mt], bh);
                    mma16816f(acc[mt][2*ntp+1], ah[mt], bh + 2);
                    mma16816f(acc[mt][2*ntp+1], al[mt], bh + 2);
                }
            }
        }
        __syncthreads();
    }

#pragma unroll
    for (int mt = 0; mt < 2; mt++) {
        int row = m0 + wm * 32 + mt * 16 + (l >> 2);
        int colb = n0 + wn * 64 + 2 * (l & 3);
#pragma unroll
        for (int nt = 0; nt < 8; nt++) {
            int col = colb + nt * 8;
            float2 v0; v0.x = acc[mt][nt][0]; v0.y = acc[mt][nt][1];
            float2 v1; v1.x = acc[mt][nt][2]; v1.y = acc[mt][nt][3];
            *(float2*)&C[(size_t)row * N + col] = v0;
            *(float2*)&C[(size_t)(row + 8) * N + col] = v1;
        }
    }
}

// ---------------- beta / g projections ----------------
#define BG_RG 4
__global__ __launch_bounds__(256) void bg_kernel(
    const float* __restrict__ hs, const float* __restrict__ W_b, const float* __restrict__ W_a,
    const float* __restrict__ dt_bias, const float* __restrict__ A_log,
    float* __restrict__ beta, float* __restrict__ gg)
{
    __shared__ float hsm[BG_RG * HIDN];
    __shared__ float red[4 * BG_RG * 64];
    int r0 = blockIdx.x * BG_RG;
    int t = threadIdx.x;
    for (int o = t; o < BG_RG * HIDN / 4; o += 256)
        ((float4*)hsm)[o] = ((const float4*)(hs + (size_t)r0 * HIDN))[o];
    __syncthreads();

    int out = t & 63, part = t >> 6;
    const float* Wp = (out < 32) ? (W_b + out) : (W_a + out - 32);
    float acc[BG_RG];
#pragma unroll
    for (int r = 0; r < BG_RG; r++) acc[r] = 0.f;
    int kbase = part * (HIDN / 4);
    for (int kk = 0; kk < HIDN / 4; kk++) {
        int k = kbase + kk;
        float w2 = Wp[(size_t)k * 32];
#pragma unroll
        for (int r = 0; r < BG_RG; r++) acc[r] += hsm[r * HIDN + k] * w2;
    }
#pragma unroll
    for (int r = 0; r < BG_RG; r++) red[(part * BG_RG + r) * 64 + out] = acc[r];
    __syncthreads();

    int rr = t >> 6, oo = t & 63;
    float s = red[(0*BG_RG+rr)*64+oo] + red[(1*BG_RG+rr)*64+oo]
            + red[(2*BG_RG+rr)*64+oo] + red[(3*BG_RG+rr)*64+oo];
    size_t row = (size_t)r0 + rr;
    if (oo < 32) {
        beta[row * 32 + oo] = 1.f / (1.f + expf(-s));
    } else {
        int h = oo - 32;
        float x = s + dt_bias[h];
        float sp = (x > 20.f) ? x : log1pf(expf(x));
        gg[row * 32 + h] = -expf(A_log[h]) * sp;
    }
}

// ---------------- conv1d(K=4 causal) + SiLU + split + l2norm(q,k) ----------------
__global__ __launch_bounds__(128) void conv_silu_kernel(
    const float* __restrict__ mixed, const float* __restrict__ conv_w,
    float* __restrict__ qn, float* __restrict__ kn, float* __restrict__ vout)
{
    int unit = blockIdx.x;
    int s0 = blockIdx.y * 8;
    int b = blockIdx.z;
    int d = threadIdx.x;
    int base = (unit < 16) ? unit * 128
             : (unit < 32) ? KEYD + (unit - 16) * 128
             : 2 * KEYD + (unit - 32) * 128;
    int c = base + d;
    const float* mb = mixed + (size_t)b * SS * CONVD + c;

    float m[11];
#pragma unroll
    for (int j = 0; j < 11; j++) {
        int sp = s0 + j - 3;
        m[j] = (sp >= 0) ? mb[(size_t)sp * CONVD] : 0.f;
    }
    float w0 = conv_w[(size_t)c*4+0], w1 = conv_w[(size_t)c*4+1],
          w2 = conv_w[(size_t)c*4+2], w3 = conv_w[(size_t)c*4+3];
    float xs[8];
#pragma unroll
    for (int sp = 0; sp < 8; sp++) {
        float a = w0*m[sp] + w1*m[sp+1] + w2*m[sp+2] + w3*m[sp+3];
        xs[sp] = a / (1.f + expf(-a));
    }

    if (unit < 32) {
        __shared__ float red[8][4];
#pragma unroll
        for (int sp = 0; sp < 8; sp++) {
            float ss = xs[sp]*xs[sp];
#pragma unroll
            for (int off = 16; off > 0; off >>= 1) ss += __shfl_down_sync(0xffffffffu, ss, off);
            if ((d & 31) == 0) red[sp][d >> 5] = ss;
        }
        __syncthreads();
        float* dst; float extra;
        if (unit < 16) { dst = qn + (((size_t)(b*HKN+unit))*SS)*128; extra = 0.08838834764831845f; }
        else           { dst = kn + (((size_t)(b*HKN+unit-16))*SS)*128; extra = 1.f; }
#pragma unroll
        for (int sp = 0; sp < 8; sp++) {
            float tot = red[sp][0]+red[sp][1]+red[sp][2]+red[sp][3];
            float scale = rsqrtf(tot + 1e-6f) * extra;
            dst[(size_t)(s0+sp)*128 + d] = xs[sp] * scale;
        }
    } else {
        float* dst = vout + (((size_t)(b*HVN+unit-32))*SS)*128;
#pragma unroll
        for (int sp = 0; sp < 8; sp++)
            dst[(size_t)(s0+sp)*128 + d] = xs[sp];
    }
}

// ---------------- chunked gated delta rule, DV split x2, W/A on tensor cores (bf16x3, unchanged) ----------------
#define DBF_OFF   148992
#define DBF_ARR   17408
#define DBF_PITCH 272
#define DELTA_SMEM_BYTES (148992 + 4*DBF_ARR)

__global__ __launch_bounds__(256, 1) void delta_kernel(
    const float* __restrict__ qn, const float* __restrict__ kn,
    const float* __restrict__ vv, const float* __restrict__ beta,
    const float* __restrict__ gg, float* __restrict__ core)
{
    extern __shared__ float sm[];
    char* smc = (char*)sm;
    uint32_t sbase = smem_u32(sm);
    float* st  = sm;          // [128][64]
    float* KT  = st + 8192;   // [128][65]
    float* Qs  = KT + 8320;   // [64][128]
    float* Vs  = Qs + 8192;   // [64][64]
    float* Wm  = Vs + 4096;   // [64][64]
    float* Am  = Wm + 4096;   // [64][64]
    float* gcs = Am + 4096;
    float* bet = gcs + 64;
    float* egs = bet + 64;
    float* edl = egs + 64;

    int t = threadIdx.x;
    int wrp = t >> 5, l = t & 31;
    int vs = blockIdx.x & 1;
    int h  = (blockIdx.x >> 1) & 31;
    int b  = blockIdx.x >> 6;
    int vo = vs * 64;
    int hk = h >> 1;
    const float* qb = qn + (size_t)(b*HKN+hk)*SS*128;
    const float* kb = kn + (size_t)(b*HKN+hk)*SS*128;
    const float* vb = vv + (size_t)(b*HVN+h)*SS*128;
    const float* bp = beta + (size_t)b*SS*HVN + h;
    const float* gp = gg   + (size_t)b*SS*HVN + h;
    float* cb = core + (size_t)(b*HVN+h)*SS*128;

    for (int i = t; i < 8192; i += 256) st[i] = 0.f;
    __syncthreads();

    for (int ck = 0; ck < NCHK; ck++) {
        size_t srow = (size_t)ck * 64;
        const float* qr = qb + srow*128;
        const float* kr = kb + srow*128;
        const float* vr = vb + srow*128;
        for (int idx = t; idx < 8192; idx += 256) {
            int i = idx >> 7, d = idx & 127;
            float kvv = kr[idx];
            float qvv = qr[idx];
            KT[d*65 + i] = kvv;
            Qs[idx] = qvv;
            __nv_bfloat16 kh = __float2bfloat16_rn(kvv);
            __nv_bfloat16 qh = __float2bfloat16_rn(qvv);
            int ro = i*DBF_PITCH + d*2;
            *(__nv_bfloat16*)(smc + DBF_OFF + 0*DBF_ARR + ro) = kh;
            *(__nv_bfloat16*)(smc + DBF_OFF + 1*DBF_ARR + ro) = __float2bfloat16_rn(kvv - __bfloat162float(kh));
            *(__nv_bfloat16*)(smc + DBF_OFF + 2*DBF_ARR + ro) = qh;
            *(__nv_bfloat16*)(smc + DBF_OFF + 3*DBF_ARR + ro) = __float2bfloat16_rn(qvv - __bfloat162float(qh));
        }
        for (int idx = t; idx < 4096; idx += 256) {
            int i = idx >> 6, c = idx & 63;
            Vs[idx] = vr[i*128 + vo + c];
        }
        if (t < 64) {
            bet[t] = bp[(srow + t)*HVN];
            edl[t] = gp[(srow + t)*HVN];
        }
        __syncthreads();
        if (t == 0) {
            float r = 0.f;
            for (int i = 0; i < 64; i++) { r += edl[i]; gcs[i] = r; }
        }
        __syncthreads();
        if (t < 64) {
            egs[t] = expf(gcs[t]);
            edl[t] = expf(gcs[63] - gcs[t]);
        }
        __syncthreads();

        // ---- W/A via HMMA bf16x3 ----
        {
            float acc[2][4][4];
#pragma unroll
            for (int a1 = 0; a1 < 2; a1++)
#pragma unroll
                for (int a2 = 0; a2 < 4; a2++)
#pragma unroll
                    for (int a3 = 0; a3 < 4; a3++) acc[a1][a2][a3] = 0.f;

            uint32_t a_row = (l & 15);
            uint32_t a_col = (l >> 4) * 16;
            uint32_t b_row = (l & 7) + ((l >> 4) << 3);
            uint32_t b_col = ((l >> 3) & 1) * 16;
#pragma unroll
            for (int tt = 0; tt < 2; tt++) {
                int tile = wrp + tt*8;
                int Dsel = tile >> 3;
                int sub = tile & 7;
                int r0 = (sub >> 1) << 4, c0g = (sub & 1) << 5;
                uint32_t ahb = sbase + DBF_OFF + (Dsel ? 2*DBF_ARR : 0);
#pragma unroll
                for (int kt = 0; kt < 8; kt++) {
                    uint32_t aaddr = ahb + (r0 + a_row)*DBF_PITCH + kt*32 + a_col;
                    uint32_t ah[4], al[4];
                    ldsm4(ah, aaddr);
                    ldsm4(al, aaddr + DBF_ARR);
#pragma unroll
                    for (int nn = 0; nn < 2; nn++) {
                        uint32_t baddr = sbase + DBF_OFF + (c0g + nn*16 + b_row)*DBF_PITCH + kt*32 + b_col;
                        uint32_t bh[4], bl[4];
                        ldsm4(bh, baddr);
                        ldsm4(bl, baddr + DBF_ARR);
                        mma16816b(acc[tt][2*nn],   ah, bh);
                        mma16816b(acc[tt][2*nn],   ah, bl);
                        mma16816b(acc[tt][2*nn],   al, bh);
                        mma16816b(acc[tt][2*nn+1], ah, bh + 2);
                        mma16816b(acc[tt][2*nn+1], ah, bl + 2);
                        mma16816b(acc[tt][2*nn+1], al, bh + 2);
                    }
                }
#pragma unroll
                for (int n8 = 0; n8 < 4; n8++) {
#pragma unroll
                    for (int e = 0; e < 4; e++) {
                        int row = r0 + (l >> 2) + ((e >> 1) ? 8 : 0);
                        int col = c0g + n8*8 + 2*(l & 3) + (e & 1);
                        float dot = acc[tt][n8][e];
                        if (Dsel == 0) {
                            float outv = 0.f;
                            if (col < row) outv = bet[row] * expf(gcs[row] - gcs[col]) * dot;
                            Wm[row*64 + col] = outv;
                        } else {
                            float outv = 0.f;
                            if (col <= row) outv = expf(gcs[row] - gcs[col]) * dot;
                            Am[row*64 + col] = outv;
                        }
                    }
                }
            }
        }
        // ---- X = beta*(v - e^{gc} * (k @ st)) ----
        {
            int r0 = (t >> 3) * 2, c0 = (t & 7) * 8;
            float acc[2][8];
#pragma unroll
            for (int i = 0; i < 2; i++)
#pragma unroll
                for (int j = 0; j < 8; j++) acc[i][j] = 0.f;
            for (int d = 0; d < 128; d++) {
                float kv0 = KT[d*65 + r0], kv1 = KT[d*65 + r0 + 1];
                float4 s0 = *(float4*)&st[d*64 + c0];
                float4 s1 = *(float4*)&st[d*64 + c0 + 4];
                float sv[8] = {s0.x,s0.y,s0.z,s0.w,s1.x,s1.y,s1.z,s1.w};
#pragma unroll
                for (int j = 0; j < 8; j++) {
                    acc[0][j] += kv0*sv[j];
                    acc[1][j] += kv1*sv[j];
                }
            }
            __syncthreads();
#pragma unroll
            for (int i = 0; i < 2; i++) {
                int r = r0 + i; float bi = bet[r], e = egs[r];
#pragma unroll
                for (int j = 0; j < 8; j++) {
                    int c = c0 + j;
                    Vs[r*64 + c] = bi*(Vs[r*64 + c] - e*acc[i][j]);
                }
            }
        }
        __syncthreads();
        // ---- forward substitution ----
        if (t < 64) {
            float x[64];
#pragma unroll
            for (int i = 0; i < 64; i++) {
                float a0 = Vs[i*64 + t], a1 = 0.f;
                int j = 0;
#pragma unroll
                for (; j + 2 <= i; j += 2) {
                    a0 -= Wm[i*64 + j]   * x[j];
                    a1 -= Wm[i*64 + j+1] * x[j+1];
                }
                if (j < i) a0 -= Wm[i*64 + j] * x[j];
                x[i] = a0 + a1;
            }
#pragma unroll
            for (int i = 0; i < 64; i++) Vs[i*64 + t] = x[i];
        }
        __syncthreads();
        // ---- out = e^{gc}*(q@st) + Am@v_new ----
        {
            int r0 = (t >> 3) * 2, c0 = (t & 7) * 8;
            float o1[2][8], o2[2][8];
#pragma unroll
            for (int i = 0; i < 2; i++)
#pragma unroll
                for (int j = 0; j < 8; j++) { o1[i][j] = 0.f; o2[i][j] = 0.f; }
            for (int d = 0; d < 128; d++) {
                float q0 = Qs[r0*128 + d], q1 = Qs[(r0+1)*128 + d];
                float4 s0 = *(float4*)&st[d*64 + c0];
                float4 s1 = *(float4*)&st[d*64 + c0 + 4];
                float sv[8] = {s0.x,s0.y,s0.z,s0.w,s1.x,s1.y,s1.z,s1.w};
#pragma unroll
                for (int j = 0; j < 8; j++) {
                    o1[0][j] += q0*sv[j];
                    o1[1][j] += q1*sv[j];
                }
            }
            for (int jj = 0; jj < 64; jj++) {
                float a0 = Am[r0*64 + jj], a1 = Am[(r0+1)*64 + jj];
                float4 v0 = *(float4*)&Vs[jj*64 + c0];
                float4 v1 = *(float4*)&Vs[jj*64 + c0 + 4];
                float vw[8] = {v0.x,v0.y,v0.z,v0.w,v1.x,v1.y,v1.z,v1.w};
#pragma unroll
                for (int j = 0; j < 8; j++) {
                    o2[0][j] += a0*vw[j];
                    o2[1][j] += a1*vw[j];
                }
            }
#pragma unroll
            for (int i = 0; i < 2; i++) {
                int r = r0 + i; float e = egs[r];
#pragma unroll
                for (int j = 0; j < 8; j += 4) {
                    float4 v;
                    v.x = e*o1[i][j]   + o2[i][j];
                    v.y = e*o1[i][j+1] + o2[i][j+1];
                    v.z = e*o1[i][j+2] + o2[i][j+2];
                    v.w = e*o1[i][j+3] + o2[i][j+3];
                    *(float4*)&cb[(srow + r)*128 + vo + c0 + j] = v;
                }
            }
        }
        __syncthreads();
        // ---- state update ----
        {
            int d0 = (t >> 3) * 4, v0 = (t & 7) * 8;
            float acc[4][8];
#pragma unroll
            for (int i = 0; i < 4; i++)
#pragma unroll
                for (int j = 0; j < 8; j++) acc[i][j] = 0.f;
            for (int i = 0; i < 64; i++) {
                float el = edl[i];
                float kv[4];
#pragma unroll
                for (int x2 = 0; x2 < 4; x2++) kv[x2] = KT[(d0+x2)*65 + i] * el;
                float4 a = *(float4*)&Vs[i*64 + v0];
                float4 bq = *(float4*)&Vs[i*64 + v0 + 4];
                float vw[8] = {a.x,a.y,a.z,a.w,bq.x,bq.y,bq.z,bq.w};
#pragma unroll
                for (int x2 = 0; x2 < 4; x2++)
#pragma unroll
                    for (int y = 0; y < 8; y++) acc[x2][y] += kv[x2]*vw[y];
            }
            float egl = expf(gcs[63]);
#pragma unroll
            for (int x2 = 0; x2 < 4; x2++)
#pragma unroll
                for (int y = 0; y < 8; y += 4) {
                    float4 s = *(float4*)&st[(d0+x2)*64 + v0 + y];
                    s.x = s.x*egl + acc[x2][y];
                    s.y = s.y*egl + acc[x2][y+1];
                    s.z = s.z*egl + acc[x2][y+2];
                    s.w = s.w*egl + acc[x2][y+3];
                    *(float4*)&st[(d0+x2)*64 + v0 + y] = s;
                }
        }
        __syncthreads();
    }
}

// ---------------- gated RMSNorm + SiLU(z) gate -> fp16 hi/lo ----------------
__global__ __launch_bounds__(128) void normgate_kernel(
    const float* __restrict__ core, const float* __restrict__ z,
    const float* __restrict__ norm_weight,
    __half* __restrict__ act_hi, __half* __restrict__ act_lo)
{
    int s = blockIdx.x, h = blockIdx.y, b = blockIdx.z;
    int d = threadIdx.x;
    __shared__ float red[4];
    size_t ci = ((size_t)(b*HVN + h)*SS + s)*128 + d;
    float v = core[ci];
    float ss = v*v;
#pragma unroll
    for (int off = 16; off > 0; off >>= 1) ss += __shfl_down_sync(0xffffffffu, ss, off);
    if ((d & 31) == 0) red[d >> 5] = ss;
    __syncthreads();
    float var = (red[0]+red[1]+red[2]+red[3]) * (1.f/128.f);
    float scale = rsqrtf(var + 1e-6f) * norm_weight[d];
    size_t zi = ((size_t)b*SS + s)*VALD + h*128 + d;
    float zv = z[zi];
    float gate = zv / (1.f + expf(-zv));
    float val = v * scale * gate;
    __half hv = __float2half_rn(val);
    act_hi[zi] = hv;
    act_lo[zi] = __float2half_rn(val - __half2float(hv));
}

extern "C" void kernel_launch(void* const* d_in, const int* in_sizes, int n_in,
                              void* d_out, int out_size) {
    const float* hs     = (const float*)d_in[0];
    const float* W_qkv  = (const float*)d_in[1];
    const float* conv_w = (const float*)d_in[2];
    const float* W_z    = (const float*)d_in[3];
    const float* W_b    = (const float*)d_in[4];
    const float* W_a    = (const float*)d_in[5];
    const float* dt_b   = (const float*)d_in[6];
    const float* A_log  = (const float*)d_in[7];
    const float* normw  = (const float*)d_in[8];
    const float* W_out  = (const float*)d_in[9];
    float* out = (float*)d_out;

    float *mixed, *z, *qn, *kn, *v, *core, *beta, *gg;
    cudaGetSymbolAddress((void**)&mixed, g_mixed);
    cudaGetSymbolAddress((void**)&z,     g_z);
    cudaGetSymbolAddress((void**)&qn,    g_qn);
    cudaGetSymbolAddress((void**)&kn,    g_kn);
    cudaGetSymbolAddress((void**)&v,     g_v);
    cudaGetSymbolAddress((void**)&core,  g_core);
    cudaGetSymbolAddress((void**)&beta,  g_beta);
    cudaGetSymbolAddress((void**)&gg,    g_gg);

    __half *hs_hi, *hs_lo, *wqkv_h, *wz_h, *wout_h, *act_hi, *act_lo;
    cudaGetSymbolAddress((void**)&hs_hi,  g_hs_hi);
    cudaGetSymbolAddress((void**)&hs_lo,  g_hs_lo);
    cudaGetSymbolAddress((void**)&wqkv_h, g_wqkv_h);
    cudaGetSymbolAddress((void**)&wz_h,   g_wz_h);
    cudaGetSymbolAddress((void**)&wout_h, g_wout_h);
    cudaGetSymbolAddress((void**)&act_hi, g_act_hi);
    cudaGetSymbolAddress((void**)&act_lo, g_act_lo);

    cudaFuncSetAttribute(delta_kernel, cudaFuncAttributeMaxDynamicSharedMemorySize, DELTA_SMEM_BYTES);
    cudaFuncSetAttribute(hmma_gemm_kernel, cudaFuncAttributeMaxDynamicSharedMemorySize, GEMM_SMEM);

    static cudaStream_t s2 = nullptr;
    static cudaEvent_t e_fork = nullptr, e_g2 = nullptr;
    if (s2 == nullptr) {
        cudaStreamCreateWithFlags(&s2, cudaStreamNonBlocking);
        cudaEventCreateWithFlags(&e_fork, cudaEventDisableTiming);
        cudaEventCreateWithFlags(&e_g2, cudaEventDisableTiming);
    }

    // 0) weight transposes (single fp16), hs split (fp16 hi/lo)
    tsplit_all_kernel<<<32768, 256>>>(W_qkv, wqkv_h, W_z, wz_h, W_out, wout_h);
    split_kernel<<<2048, 256>>>(hs, hs_hi, hs_lo, (size_t)MROWS*HIDN);

    // 1) mixed = hs @ W_qkv
    hmma_gemm_kernel<<<dim3(MROWS/128, CONVD/128), 256, GEMM_SMEM>>>(
        hs_hi, hs_lo, wqkv_h, mixed, MROWS, CONVD, HIDN);

    // fork: z-projection on side stream
    cudaEventRecord(e_fork, 0);
    cudaStreamWaitEvent(s2, e_fork, 0);
    hmma_gemm_kernel<<<dim3(MROWS/128, VALD/128), 256, GEMM_SMEM, s2>>>(
        hs_hi, hs_lo, wz_h, z, MROWS, VALD, HIDN);
    cudaEventRecord(e_g2, s2);

    // main chain
    bg_kernel<<<MROWS/BG_RG, 256>>>(hs, W_b, W_a, dt_b, A_log, beta, gg);
    conv_silu_kernel<<<dim3(64, SS/8, BB), 128>>>(mixed, conv_w, qn, kn, v);
    delta_kernel<<<BB*HVN*2, 256, DELTA_SMEM_BYTES>>>(qn, kn, v, beta, gg, core);

    // join: normgate needs z
    cudaStreamWaitEvent(0, e_g2, 0);
    normgate_kernel<<<dim3(SS, HVN, BB), 128>>>(core, z, normw, act_hi, act_lo);

    // out = act @ W_out
    hmma_gemm_kernel<<<dim3(MROWS/128, HIDN/128), 256, GEMM_SMEM>>>(
        act_hi, act_lo, wout_h, out, MROWS, HIDN, VALD);
}

// round 13
// speedup vs baseline: 1.5846x; 1.1771x over previous
#include <cuda_runtime.h>
#include <cuda_bf16.h>
#include <cuda_fp16.h>
#include <math.h>
#include <stdint.h>

#define BB    2
#define SS    4096
#define HIDN  2048
#define HVN   32
#define HKN   16
#define CONVD 8192
#define KEYD  2048
#define VALD  4096
#define NCHK  64
#define MROWS (BB*SS)

// ---------------- device scratch ----------------
__device__ float g_mixed[(size_t)BB*SS*CONVD];
__device__ float g_z    [(size_t)BB*SS*VALD];
__device__ float g_qn   [(size_t)BB*HKN*SS*128];
__device__ float g_kn   [(size_t)BB*HKN*SS*128];
__device__ float g_v    [(size_t)BB*HVN*SS*128];
__device__ float g_core [(size_t)BB*HVN*SS*128];
__device__ float g_beta [(size_t)BB*SS*HVN];
__device__ float g_gg   [(size_t)BB*SS*HVN];

__device__ __half g_hs_hi [(size_t)MROWS*HIDN];
__device__ __half g_hs_lo [(size_t)MROWS*HIDN];
__device__ __half g_wqkv_h[(size_t)CONVD*HIDN];  // [N,K]
__device__ __half g_wz_h  [(size_t)VALD*HIDN];
__device__ __half g_wout_h[(size_t)HIDN*VALD];
__device__ __half g_act_hi[(size_t)MROWS*VALD];
__device__ __half g_act_lo[(size_t)MROWS*VALD];

// ---------------- helpers ----------------
__device__ __forceinline__ uint32_t smem_u32(const void* p) {
    uint32_t a;
    asm("{ .reg .u64 t; cvta.to.shared.u64 t, %1; cvt.u32.u64 %0, t; }" : "=r"(a) : "l"(p));
    return a;
}
__device__ __forceinline__ void ldsm4(uint32_t* r, uint32_t addr) {
    asm volatile("ldmatrix.sync.aligned.m8n8.x4.shared.b16 {%0,%1,%2,%3}, [%4];"
        : "=r"(r[0]), "=r"(r[1]), "=r"(r[2]), "=r"(r[3]) : "r"(addr));
}
__device__ __forceinline__ void mma16816f(float* c, const uint32_t* a, const uint32_t* b) {
    asm volatile("mma.sync.aligned.m16n8k16.row.col.f32.f16.f16.f32 "
        "{%0,%1,%2,%3}, {%4,%5,%6,%7}, {%8,%9}, {%0,%1,%2,%3};"
        : "+f"(c[0]), "+f"(c[1]), "+f"(c[2]), "+f"(c[3])
        : "r"(a[0]), "r"(a[1]), "r"(a[2]), "r"(a[3]), "r"(b[0]), "r"(b[1]));
}
__device__ __forceinline__ void mma16816b(float* c, const uint32_t* a, const uint32_t* b) {
    asm volatile("mma.sync.aligned.m16n8k16.row.col.f32.bf16.bf16.f32 "
        "{%0,%1,%2,%3}, {%4,%5,%6,%7}, {%8,%9}, {%0,%1,%2,%3};"
        : "+f"(c[0]), "+f"(c[1]), "+f"(c[2]), "+f"(c[3])
        : "r"(a[0]), "r"(a[1]), "r"(a[2]), "r"(a[3]), "r"(b[0]), "r"(b[1]));
}
__device__ __forceinline__ void cp16(uint32_t dst, const void* src) {
    asm volatile("cp.async.cg.shared.global [%0], [%1], 16;" :: "r"(dst), "l"(src));
}

// ---------------- split kernels (fp16 hi/lo) ----------------
__global__ __launch_bounds__(256) void split_kernel(
    const float* __restrict__ in, __half* __restrict__ hi, __half* __restrict__ lo, size_t n)
{
    size_t i = (size_t)blockIdx.x * 256 + threadIdx.x;
    size_t stride = (size_t)gridDim.x * 256;
    for (; i < n; i += stride) {
        float v = in[i];
        __half h = __float2half_rn(v);
        hi[i] = h;
        lo[i] = __float2half_rn(v - __half2float(h));
    }
}

__global__ __launch_bounds__(256) void tsplit_all_kernel(
    const float* __restrict__ Wq, __half* __restrict__ qh,
    const float* __restrict__ Wz, __half* __restrict__ zh,
    const float* __restrict__ Wo, __half* __restrict__ oh)
{
    __shared__ float tile[32][33];
    int n = blockIdx.x;
    const float* W; __half* Thi; int K, N, bx, by;
    if (n < 16384)      { W = Wq; Thi = qh; K = HIDN; N = CONVD; bx = n & 255; by = n >> 8; }
    else if (n < 24576) { n -= 16384; W = Wz; Thi = zh; K = HIDN; N = VALD; bx = n & 127; by = n >> 7; }
    else                { n -= 24576; W = Wo; Thi = oh; K = VALD; N = HIDN; bx = n & 63;  by = n >> 6; }
    int tx = threadIdx.x & 31, ty = threadIdx.x >> 5;
    for (int i = ty; i < 32; i += 8)
        tile[i][tx] = W[(size_t)(by*32 + i) * N + bx*32 + tx];
    __syncthreads();
    for (int i = ty; i < 32; i += 8)
        Thi[(size_t)(bx*32 + i) * K + by*32 + tx] = __float2half_rn(tile[tx][i]);
}

// ---------------- HMMA fp16x2 GEMM (unchanged, proven) ----------------
#define GS_ROW   80
#define GS_ARR   (128*GS_ROW)
#define GS_STAGE (3*GS_ARR)
#define GEMM_SMEM (2*GS_STAGE)

__global__ __launch_bounds__(256, 2) void hmma_gemm_kernel(
    const __half* __restrict__ Ahi, const __half* __restrict__ Alo,
    const __half* __restrict__ Bh,
    float* __restrict__ C, int M, int N, int K)
{
    extern __shared__ char smem[];
    uint32_t sb = smem_u32(smem);
    int t = threadIdx.x;
    int m0 = blockIdx.x * 128;
    int n0 = blockIdx.y * 128;
    int w = t >> 5, l = t & 31;
    int wm = w & 3, wn = w >> 2;

    const __half* srcs[3] = { Ahi, Alo, Bh };
    int rowbase[3];
    rowbase[0] = m0; rowbase[1] = m0; rowbase[2] = n0;

    float acc[2][8][4];
#pragma unroll
    for (int i = 0; i < 2; i++)
#pragma unroll
        for (int j = 0; j < 8; j++)
#pragma unroll
            for (int r = 0; r < 4; r++) acc[i][j][r] = 0.f;

    int KT = K >> 5;

    auto load_stage = [&](int s, int k0) {
        uint32_t stb = sb + s * GS_STAGE;
#pragma unroll
        for (int c = 0; c < 6; c++) {
            int idx = t + c * 256;
            int arr = idx >> 9;
            int within = idx & 511;
            int row = within >> 2, ch = within & 3;
            const __half* src = srcs[arr] + (size_t)(rowbase[arr] + row) * K + k0 + ch * 8;
            cp16(stb + arr * GS_ARR + row * GS_ROW + ch * 16, src);
        }
        asm volatile("cp.async.commit_group;");
    };

    load_stage(0, 0);

    int a_off = (wm * 32 + (l & 15)) * GS_ROW + ((l >> 4) * 16);
    int b_off = (wn * 64 + (l & 7) + ((l >> 4) << 3)) * GS_ROW + (((l >> 3) & 1) * 16);

    for (int kt = 0; kt < KT; kt++) {
        if (kt + 1 < KT) load_stage((kt + 1) & 1, (kt + 1) << 5);
        if (kt + 1 < KT) asm volatile("cp.async.wait_group 1;");
        else             asm volatile("cp.async.wait_group 0;");
        __syncthreads();

        uint32_t stb = sb + (kt & 1) * GS_STAGE;
#pragma unroll
        for (int ks = 0; ks < 2; ks++) {
            uint32_t ah[2][4], al[2][4];
#pragma unroll
            for (int mt = 0; mt < 2; mt++) {
                uint32_t aa = stb + a_off + mt * 16 * GS_ROW + ks * 32;
                ldsm4(ah[mt], aa);
                ldsm4(al[mt], aa + GS_ARR);
            }
#pragma unroll
            for (int ntp = 0; ntp < 4; ntp++) {
                uint32_t ba = stb + 2 * GS_ARR + b_off + ntp * 16 * GS_ROW + ks * 32;
                uint32_t bh[4];
                ldsm4(bh, ba);
#pragma unroll
                for (int mt = 0; mt < 2; mt++) {
                    mma16816f(acc[mt][2*ntp],   ah[mt], bh);
                    mma16816f(acc[mt][2*ntp],   al[mt], bh);
                    mma16816f(acc[mt][2*ntp+1], ah[mt], bh + 2);
                    mma16816f(acc[mt][2*ntp+1], al[mt], bh + 2);
                }
            }
        }
        __syncthreads();
    }

#pragma unroll
    for (int mt = 0; mt < 2; mt++) {
        int row = m0 + wm * 32 + mt * 16 + (l >> 2);
        int colb = n0 + wn * 64 + 2 * (l & 3);
#pragma unroll
        for (int nt = 0; nt < 8; nt++) {
            int col = colb + nt * 8;
            float2 v0; v0.x = acc[mt][nt][0]; v0.y = acc[mt][nt][1];
            float2 v1; v1.x = acc[mt][nt][2]; v1.y = acc[mt][nt][3];
            *(float2*)&C[(size_t)row * N + col] = v0;
            *(float2*)&C[(size_t)(row + 8) * N + col] = v1;
        }
    }
}

// ---------------- beta / g projections ----------------
#define BG_RG 4
__global__ __launch_bounds__(256) void bg_kernel(
    const float* __restrict__ hs, const float* __restrict__ W_b, const float* __restrict__ W_a,
    const float* __restrict__ dt_bias, const float* __restrict__ A_log,
    float* __restrict__ beta, float* __restrict__ gg)
{
    __shared__ float hsm[BG_RG * HIDN];
    __shared__ float red[4 * BG_RG * 64];
    int r0 = blockIdx.x * BG_RG;
    int t = threadIdx.x;
    for (int o = t; o < BG_RG * HIDN / 4; o += 256)
        ((float4*)hsm)[o] = ((const float4*)(hs + (size_t)r0 * HIDN))[o];
    __syncthreads();

    int out = t & 63, part = t >> 6;
    const float* Wp = (out < 32) ? (W_b + out) : (W_a + out - 32);
    float acc[BG_RG];
#pragma unroll
    for (int r = 0; r < BG_RG; r++) acc[r] = 0.f;
    int kbase = part * (HIDN / 4);
    for (int kk = 0; kk < HIDN / 4; kk++) {
        int k = kbase + kk;
        float w2 = Wp[(size_t)k * 32];
#pragma unroll
        for (int r = 0; r < BG_RG; r++) acc[r] += hsm[r * HIDN + k] * w2;
    }
#pragma unroll
    for (int r = 0; r < BG_RG; r++) red[(part * BG_RG + r) * 64 + out] = acc[r];
    __syncthreads();

    int rr = t >> 6, oo = t & 63;
    float s = red[(0*BG_RG+rr)*64+oo] + red[(1*BG_RG+rr)*64+oo]
            + red[(2*BG_RG+rr)*64+oo] + red[(3*BG_RG+rr)*64+oo];
    size_t row = (size_t)r0 + rr;
    if (oo < 32) {
        beta[row * 32 + oo] = 1.f / (1.f + expf(-s));
    } else {
        int h = oo - 32;
        float x = s + dt_bias[h];
        float sp = (x > 20.f) ? x : log1pf(expf(x));
        gg[row * 32 + h] = -expf(A_log[h]) * sp;
    }
}

// ---------------- conv1d(K=4 causal) + SiLU + split + l2norm(q,k) ----------------
__global__ __launch_bounds__(128) void conv_silu_kernel(
    const float* __restrict__ mixed, const float* __restrict__ conv_w,
    float* __restrict__ qn, float* __restrict__ kn, float* __restrict__ vout)
{
    int unit = blockIdx.x;
    int s0 = blockIdx.y * 8;
    int b = blockIdx.z;
    int d = threadIdx.x;
    int base = (unit < 16) ? unit * 128
             : (unit < 32) ? KEYD + (unit - 16) * 128
             : 2 * KEYD + (unit - 32) * 128;
    int c = base + d;
    const float* mb = mixed + (size_t)b * SS * CONVD + c;

    float m[11];
#pragma unroll
    for (int j = 0; j < 11; j++) {
        int sp = s0 + j - 3;
        m[j] = (sp >= 0) ? mb[(size_t)sp * CONVD] : 0.f;
    }
    float w0 = conv_w[(size_t)c*4+0], w1 = conv_w[(size_t)c*4+1],
          w2 = conv_w[(size_t)c*4+2], w3 = conv_w[(size_t)c*4+3];
    float xs[8];
#pragma unroll
    for (int sp = 0; sp < 8; sp++) {
        float a = w0*m[sp] + w1*m[sp+1] + w2*m[sp+2] + w3*m[sp+3];
        xs[sp] = a / (1.f + expf(-a));
    }

    if (unit < 32) {
        __shared__ float red[8][4];
#pragma unroll
        for (int sp = 0; sp < 8; sp++) {
            float ss = xs[sp]*xs[sp];
#pragma unroll
            for (int off = 16; off > 0; off >>= 1) ss += __shfl_down_sync(0xffffffffu, ss, off);
            if ((d & 31) == 0) red[sp][d >> 5] = ss;
        }
        __syncthreads();
        float* dst; float extra;
        if (unit < 16) { dst = qn + (((size_t)(b*HKN+unit))*SS)*128; extra = 0.08838834764831845f; }
        else           { dst = kn + (((size_t)(b*HKN+unit-16))*SS)*128; extra = 1.f; }
#pragma unroll
        for (int sp = 0; sp < 8; sp++) {
            float tot = red[sp][0]+red[sp][1]+red[sp][2]+red[sp][3];
            float scale = rsqrtf(tot + 1e-6f) * extra;
            dst[(size_t)(s0+sp)*128 + d] = xs[sp] * scale;
        }
    } else {
        float* dst = vout + (((size_t)(b*HVN+unit-32))*SS)*128;
#pragma unroll
        for (int sp = 0; sp < 8; sp++)
            dst[(size_t)(s0+sp)*128 + d] = xs[sp];
    }
}

// ---------------- chunked gated delta rule: W/A/X'/O1 all on tensor cores ----------------
// fp32 (floats): st[64v][128d] 8192 | KT[128][65] 8320 | Vs[64][64] 4096 | Wm 4096 | Am 4096 | scalars 256
// bf16 staging after fp32 (byte offset 116224): Khi Klo Qhi Qlo SThi STlo, each 64x272B = 17408B
#define DBF_OFF   116224
#define DBF_ARR   17408
#define DBF_PITCH 272
#define DOF_K     0
#define DOF_Q     34816
#define DOF_ST    69632
#define DELTA_SMEM_BYTES (116224 + 6*17408)   // 220672

__global__ __launch_bounds__(256, 1) void delta_kernel(
    const float* __restrict__ qn, const float* __restrict__ kn,
    const float* __restrict__ vv, const float* __restrict__ beta,
    const float* __restrict__ gg, float* __restrict__ core)
{
    extern __shared__ float sm[];
    char* smc = (char*)sm;
    uint32_t sbase = smem_u32(sm);
    float* st  = sm;          // [64 v][128 d]
    float* KT  = st + 8192;   // [128 d][65] (k transposed)
    float* Vs  = KT + 8320;   // [64 i][64 v]
    float* Wm  = Vs + 4096;   // [64][64]
    float* Am  = Wm + 4096;   // [64][64]
    float* gcs = Am + 4096;
    float* bet = gcs + 64;
    float* egs = bet + 64;
    float* edl = egs + 64;

    int t = threadIdx.x;
    int wrp = t >> 5, l = t & 31;
    int vs = blockIdx.x & 1;
    int h  = (blockIdx.x >> 1) & 31;
    int b  = blockIdx.x >> 6;
    int vo = vs * 64;
    int hk = h >> 1;
    const float* qb = qn + (size_t)(b*HKN+hk)*SS*128;
    const float* kb = kn + (size_t)(b*HKN+hk)*SS*128;
    const float* vb = vv + (size_t)(b*HVN+h)*SS*128;
    const float* bp = beta + (size_t)b*SS*HVN + h;
    const float* gp = gg   + (size_t)b*SS*HVN + h;
    float* cb = core + (size_t)(b*HVN+h)*SS*128;

    for (int i = t; i < 8192; i += 256) st[i] = 0.f;
    __syncthreads();

    for (int ck = 0; ck < NCHK; ck++) {
        size_t srow = (size_t)ck * 64;
        const float* qr = qb + srow*128;
        const float* kr = kb + srow*128;
        const float* vr = vb + srow*128;
        // stage k,q (fp32 KT + bf16 hi/lo) and st (bf16 hi/lo, from previous chunk)
        for (int idx = t; idx < 8192; idx += 256) {
            int i = idx >> 7, d = idx & 127;
            int ro = i*DBF_PITCH + d*2;
            float kvv = kr[idx];
            float qvv = qr[idx];
            KT[d*65 + i] = kvv;
            __nv_bfloat16 kh = __float2bfloat16_rn(kvv);
            __nv_bfloat16 qh = __float2bfloat16_rn(qvv);
            *(__nv_bfloat16*)(smc + DBF_OFF + DOF_K + ro) = kh;
            *(__nv_bfloat16*)(smc + DBF_OFF + DOF_K + DBF_ARR + ro) = __float2bfloat16_rn(kvv - __bfloat162float(kh));
            *(__nv_bfloat16*)(smc + DBF_OFF + DOF_Q + ro) = qh;
            *(__nv_bfloat16*)(smc + DBF_OFF + DOF_Q + DBF_ARR + ro) = __float2bfloat16_rn(qvv - __bfloat162float(qh));
            float sv = st[idx];   // st[v][d], idx = v*128+d, row v = i here
            __nv_bfloat16 sh = __float2bfloat16_rn(sv);
            *(__nv_bfloat16*)(smc + DBF_OFF + DOF_ST + ro) = sh;
            *(__nv_bfloat16*)(smc + DBF_OFF + DOF_ST + DBF_ARR + ro) = __float2bfloat16_rn(sv - __bfloat162float(sh));
        }
        for (int idx = t; idx < 4096; idx += 256) {
            int i = idx >> 6, c = idx & 63;
            Vs[idx] = vr[i*128 + vo + c];
        }
        if (t < 64) {
            bet[t] = bp[(srow + t)*HVN];
            edl[t] = gp[(srow + t)*HVN];
        }
        __syncthreads();
        if (t == 0) {
            float r = 0.f;
            for (int i = 0; i < 64; i++) { r += edl[i]; gcs[i] = r; }
        }
        __syncthreads();
        if (t < 64) {
            egs[t] = expf(gcs[t]);
            edl[t] = expf(gcs[63] - gcs[t]);
        }
        __syncthreads();

        // ---- 4 tensor products (bf16x3): 0:W=K.K^T  1:A=Q.K^T  2:X'=K.S^T  3:O1=Q.S^T
        {
            uint32_t a_row = (l & 15);
            uint32_t a_col = (l >> 4) * 16;
            uint32_t b_row = (l & 7) + ((l >> 4) << 3);
            uint32_t b_col = ((l >> 3) & 1) * 16;
#pragma unroll
            for (int tt = 0; tt < 4; tt++) {
                int tile = wrp + tt*8;
                int prod = tile >> 3;
                int sub = tile & 7;
                int r0 = (sub >> 1) << 4, c0g = (sub & 1) << 5;
                uint32_t abase = sbase + DBF_OFF + ((prod & 1) ? DOF_Q : DOF_K);
                uint32_t bbase = sbase + DBF_OFF + ((prod >> 1) ? DOF_ST : DOF_K);
                float acc[4][4];
#pragma unroll
                for (int a2 = 0; a2 < 4; a2++)
#pragma unroll
                    for (int a3 = 0; a3 < 4; a3++) acc[a2][a3] = 0.f;
#pragma unroll
                for (int kt = 0; kt < 8; kt++) {
                    uint32_t aaddr = abase + (r0 + a_row)*DBF_PITCH + kt*32 + a_col;
                    uint32_t ah[4], al[4];
                    ldsm4(ah, aaddr);
                    ldsm4(al, aaddr + DBF_ARR);
#pragma unroll
                    for (int nn = 0; nn < 2; nn++) {
                        uint32_t baddr = bbase + (c0g + nn*16 + b_row)*DBF_PITCH + kt*32 + b_col;
                        uint32_t bh[4], bl[4];
                        ldsm4(bh, baddr);
                        ldsm4(bl, baddr + DBF_ARR);
                        mma16816b(acc[2*nn],   ah, bh);
                        mma16816b(acc[2*nn],   ah, bl);
                        mma16816b(acc[2*nn],   al, bh);
                        mma16816b(acc[2*nn+1], ah, bh + 2);
                        mma16816b(acc[2*nn+1], ah, bl + 2);
                        mma16816b(acc[2*nn+1], al, bh + 2);
                    }
                }
#pragma unroll
                for (int n8 = 0; n8 < 4; n8++) {
#pragma unroll
                    for (int e = 0; e < 4; e++) {
                        int row = r0 + (l >> 2) + ((e >> 1) ? 8 : 0);
                        int col = c0g + n8*8 + 2*(l & 3) + (e & 1);
                        float dot = acc[n8][e];
                        if (prod == 0) {
                            float outv = 0.f;
                            if (col < row) outv = bet[row] * expf(gcs[row] - gcs[col]) * dot;
                            Wm[row*64 + col] = outv;
                        } else if (prod == 1) {
                            float outv = 0.f;
                            if (col <= row) outv = expf(gcs[row] - gcs[col]) * dot;
                            Am[row*64 + col] = outv;
                        } else if (prod == 2) {
                            Vs[row*64 + col] = bet[row] * (Vs[row*64 + col] - egs[row] * dot);
                        } else {
                            cb[(srow + row)*128 + vo + col] = egs[row] * dot;
                        }
                    }
                }
            }
        }
        __syncthreads();
        // ---- forward substitution: v_new = (I+W)^{-1} X  (Vs in place) ----
        if (t < 64) {
            float x[64];
#pragma unroll
            for (int i = 0; i < 64; i++) {
                float a0 = Vs[i*64 + t], a1 = 0.f;
                int j = 0;
#pragma unroll
                for (; j + 2 <= i; j += 2) {
                    a0 -= Wm[i*64 + j]   * x[j];
                    a1 -= Wm[i*64 + j+1] * x[j+1];
                }
                if (j < i) a0 -= Wm[i*64 + j] * x[j];
                x[i] = a0 + a1;
            }
#pragma unroll
            for (int i = 0; i < 64; i++) Vs[i*64 + t] = x[i];
        }
        __syncthreads();
        // ---- out: cb += Am @ v_new  (O1 term already in cb) ----
        {
            int r0 = (t >> 3) * 2, c0 = (t & 7) * 8;
            float o2[2][8];
#pragma unroll
            for (int i = 0; i < 2; i++)
#pragma unroll
                for (int j = 0; j < 8; j++) o2[i][j] = 0.f;
            for (int jj = 0; jj < 64; jj++) {
                float a0 = Am[r0*64 + jj], a1 = Am[(r0+1)*64 + jj];
                float4 v0 = *(float4*)&Vs[jj*64 + c0];
                float4 v1 = *(float4*)&Vs[jj*64 + c0 + 4];
                float vw[8] = {v0.x,v0.y,v0.z,v0.w,v1.x,v1.y,v1.z,v1.w};
#pragma unroll
                for (int j = 0; j < 8; j++) {
                    o2[0][j] += a0*vw[j];
                    o2[1][j] += a1*vw[j];
                }
            }
#pragma unroll
            for (int i = 0; i < 2; i++) {
                int r = r0 + i;
#pragma unroll
                for (int j = 0; j < 8; j += 4) {
                    float4 v = *(float4*)&cb[(srow + r)*128 + vo + c0 + j];
                    v.x += o2[i][j];
                    v.y += o2[i][j+1];
                    v.z += o2[i][j+2];
                    v.w += o2[i][j+3];
                    *(float4*)&cb[(srow + r)*128 + vo + c0 + j] = v;
                }
            }
        }
        // ---- state update: st[v][d] = st*e^{gl} + sum_i vn[i][v]*edl[i]*k[i][d] ----
        {
            int d0 = (t >> 4) * 8, v0 = (t & 15) * 4;
            float acc[4][8];
#pragma unroll
            for (int i = 0; i < 4; i++)
#pragma unroll
                for (int j = 0; j < 8; j++) acc[i][j] = 0.f;
            for (int i = 0; i < 64; i++) {
                float el = edl[i];
                float vn[4];
#pragma unroll
                for (int x2 = 0; x2 < 4; x2++) vn[x2] = Vs[i*64 + v0 + x2] * el;
                float kd[8];
#pragma unroll
                for (int j = 0; j < 8; j++) kd[j] = KT[(d0+j)*65 + i];
#pragma unroll
                for (int x2 = 0; x2 < 4; x2++)
#pragma unroll
                    for (int j = 0; j < 8; j++) acc[x2][j] += vn[x2]*kd[j];
            }
            float egl = expf(gcs[63]);
#pragma unroll
            for (int x2 = 0; x2 < 4; x2++)
#pragma unroll
                for (int j = 0; j < 8; j += 4) {
                    float4 s = *(float4*)&st[(v0+x2)*128 + d0 + j];
                    s.x = s.x*egl + acc[x2][j];
                    s.y = s.y*egl + acc[x2][j+1];
                    s.z = s.z*egl + acc[x2][j+2];
                    s.w = s.w*egl + acc[x2][j+3];
                    *(float4*)&st[(v0+x2)*128 + d0 + j] = s;
                }
        }
        __syncthreads();
    }
}

// ---------------- gated RMSNorm + SiLU(z) gate -> fp16 hi/lo ----------------
__global__ __launch_bounds__(128) void normgate_kernel(
    const float* __restrict__ core, const float* __restrict__ z,
    const float* __restrict__ norm_weight,
    __half* __restrict__ act_hi, __half* __restrict__ act_lo)
{
    int s = blockIdx.x, h = blockIdx.y, b = blockIdx.z;
    int d = threadIdx.x;
    __shared__ float red[4];
    size_t ci = ((size_t)(b*HVN + h)*SS + s)*128 + d;
    float v = core[ci];
    float ss = v*v;
#pragma unroll
    for (int off = 16; off > 0; off >>= 1) ss += __shfl_down_sync(0xffffffffu, ss, off);
    if ((d & 31) == 0) red[d >> 5] = ss;
    __syncthreads();
    float var = (red[0]+red[1]+red[2]+red[3]) * (1.f/128.f);
    float scale = rsqrtf(var + 1e-6f) * norm_weight[d];
    size_t zi = ((size_t)b*SS + s)*VALD + h*128 + d;
    float zv = z[zi];
    float gate = zv / (1.f + expf(-zv));
    float val = v * scale * gate;
    __half hv = __float2half_rn(val);
    act_hi[zi] = hv;
    act_lo[zi] = __float2half_rn(val - __half2float(hv));
}

extern "C" void kernel_launch(void* const* d_in, const int* in_sizes, int n_in,
                              void* d_out, int out_size) {
    const float* hs     = (const float*)d_in[0];
    const float* W_qkv  = (const float*)d_in[1];
    const float* conv_w = (const float*)d_in[2];
    const float* W_z    = (const float*)d_in[3];
    const float* W_b    = (const float*)d_in[4];
    const float* W_a    = (const float*)d_in[5];
    const float* dt_b   = (const float*)d_in[6];
    const float* A_log  = (const float*)d_in[7];
    const float* normw  = (const float*)d_in[8];
    const float* W_out  = (const float*)d_in[9];
    float* out = (float*)d_out;

    float *mixed, *z, *qn, *kn, *v, *core, *beta, *gg;
    cudaGetSymbolAddress((void**)&mixed, g_mixed);
    cudaGetSymbolAddress((void**)&z,     g_z);
    cudaGetSymbolAddress((void**)&qn,    g_qn);
    cudaGetSymbolAddress((void**)&kn,    g_kn);
    cudaGetSymbolAddress((void**)&v,     g_v);
    cudaGetSymbolAddress((void**)&core,  g_core);
    cudaGetSymbolAddress((void**)&beta,  g_beta);
    cudaGetSymbolAddress((void**)&gg,    g_gg);

    __half *hs_hi, *hs_lo, *wqkv_h, *wz_h, *wout_h, *act_hi, *act_lo;
    cudaGetSymbolAddress((void**)&hs_hi,  g_hs_hi);
    cudaGetSymbolAddress((void**)&hs_lo,  g_hs_lo);
    cudaGetSymbolAddress((void**)&wqkv_h, g_wqkv_h);
    cudaGetSymbolAddress((void**)&wz_h,   g_wz_h);
    cudaGetSymbolAddress((void**)&wout_h, g_wout_h);
    cudaGetSymbolAddress((void**)&act_hi, g_act_hi);
    cudaGetSymbolAddress((void**)&act_lo, g_act_lo);

    cudaFuncSetAttribute(delta_kernel, cudaFuncAttributeMaxDynamicSharedMemorySize, DELTA_SMEM_BYTES);
    cudaFuncSetAttribute(hmma_gemm_kernel, cudaFuncAttributeMaxDynamicSharedMemorySize, GEMM_SMEM);

    static cudaStream_t s2 = nullptr;
    static cudaEvent_t e_fork = nullptr, e_g2 = nullptr;
    if (s2 == nullptr) {
        cudaStreamCreateWithFlags(&s2, cudaStreamNonBlocking);
        cudaEventCreateWithFlags(&e_fork, cudaEventDisableTiming);
        cudaEventCreateWithFlags(&e_g2, cudaEventDisableTiming);
    }

    // 0) weight transposes, hs split
    tsplit_all_kernel<<<32768, 256>>>(W_qkv, wqkv_h, W_z, wz_h, W_out, wout_h);
    split_kernel<<<2048, 256>>>(hs, hs_hi, hs_lo, (size_t)MROWS*HIDN);

    // fork EARLY: gemm2 depends only on splits, runs alongside gemm1 + conv chain
    cudaEventRecord(e_fork, 0);
    cudaStreamWaitEvent(s2, e_fork, 0);
    hmma_gemm_kernel<<<dim3(MROWS/128, VALD/128), 256, GEMM_SMEM, s2>>>(
        hs_hi, hs_lo, wz_h, z, MROWS, VALD, HIDN);
    cudaEventRecord(e_g2, s2);

    // 1) mixed = hs @ W_qkv
    hmma_gemm_kernel<<<dim3(MROWS/128, CONVD/128), 256, GEMM_SMEM>>>(
        hs_hi, hs_lo, wqkv_h, mixed, MROWS, CONVD, HIDN);

    // main chain
    bg_kernel<<<MROWS/BG_RG, 256>>>(hs, W_b, W_a, dt_b, A_log, beta, gg);
    conv_silu_kernel<<<dim3(64, SS/8, BB), 128>>>(mixed, conv_w, qn, kn, v);
    delta_kernel<<<BB*HVN*2, 256, DELTA_SMEM_BYTES>>>(qn, kn, v, beta, gg, core);

    // join: normgate needs z
    cudaStreamWaitEvent(0, e_g2, 0);
    normgate_kernel<<<dim3(SS, HVN, BB), 128>>>(core, z, normw, act_hi, act_lo);

    // out = act @ W_out
    hmma_gemm_kernel<<<dim3(MROWS/128, HIDN/128), 256, GEMM_SMEM>>>(
        act_hi, act_lo, wout_h, out, MROWS, HIDN, VALD);
}